// round 3
// baseline (speedup 1.0000x reference)
#include <cuda_runtime.h>

#define BB 8
#define NN 2048

// ---------------- scratch (device globals; allocation-free) ----------------
__device__ float g_L   [BB*(size_t)NN*NN];   // Laplacian / adjacency (in-place)
__device__ float g_sq  [BB*NN];
__device__ float g_dinv[BB*NN];
__device__ float g_X0  [BB*NN*22];
__device__ float g_Ta  [BB*NN*512];
__device__ float g_Tb  [BB*NN*512];
__device__ float g_pre [BB*NN*1024];
__device__ float g_act0[BB*NN*128];
__device__ float g_skip[BB*NN*512];
__device__ float g_act2[BB*NN*1024];
__device__ float g_fc0 [BB*NN*512];
__device__ float g_fc1 [BB*NN*128];

// ---------------- generic tiled SGEMM ----------------
// MODE 0: C = A@B
// MODE 1: C += A@B
// MODE 2: C = 2*A@B - D        (cheb recursion; C may alias D)
// MODE 3: C = exp(2*A@B^T - sq[row] - sq[col])   (adjacency; TB=true, D=sq)
template<int BM,int BN,int BK,int TM,int TN,int MODE,bool TB>
__global__ void __launch_bounds__((BM/TM)*(BN/TN))
gemm_k(const float* __restrict__ A, const float* __restrict__ Bm,
       float* C, const float* D,
       int M, int N, int K,
       long long sA, long long sB, long long sC, long long sD)
{
    constexpr int NT = (BM/TM)*(BN/TN);
    const int bz = blockIdx.z;
    A  += (long long)bz * sA;
    Bm += (long long)bz * sB;
    C  += (long long)bz * sC;
    if (D) D += (long long)bz * sD;

    const int row0 = blockIdx.y * BM;
    const int col0 = blockIdx.x * BN;

    __shared__ float As[BK][BM+4];
    __shared__ float Bs[BK][BN+4];

    const int tid = threadIdx.x;
    const int tx  = tid % (BN/TN);
    const int ty  = tid / (BN/TN);

    float acc[TM][TN];
#pragma unroll
    for (int i=0;i<TM;i++)
#pragma unroll
        for (int j=0;j<TN;j++) acc[i][j] = 0.f;

    for (int k0 = 0; k0 < K; k0 += BK) {
        // load A tile (BM x BK), consecutive threads walk k (coalesced-ish)
#pragma unroll
        for (int idx = tid; idx < BM*BK; idx += NT) {
            int m  = idx / BK, kk = idx % BK;
            int gm = row0 + m, gk = k0 + kk;
            As[kk][m] = (gm < M && gk < K) ? A[(long long)gm*K + gk] : 0.f;
        }
        // load B tile (BK x BN)
        if (TB) {
            // B logically [N,K] row-major; consecutive threads walk k (contiguous)
#pragma unroll
            for (int idx = tid; idx < BK*BN; idx += NT) {
                int n  = idx / BK, kk = idx % BK;
                int gn = col0 + n, gk = k0 + kk;
                Bs[kk][n] = (gn < N && gk < K) ? Bm[(long long)gn*K + gk] : 0.f;
            }
        } else {
            // B [K,N] row-major; consecutive threads walk n (coalesced)
#pragma unroll
            for (int idx = tid; idx < BK*BN; idx += NT) {
                int kk = idx / BN, n = idx % BN;
                int gk = k0 + kk, gn = col0 + n;
                Bs[kk][n] = (gk < K && gn < N) ? Bm[(long long)gk*N + gn] : 0.f;
            }
        }
        __syncthreads();

#pragma unroll
        for (int kk = 0; kk < BK; ++kk) {
            float a[TM], b[TN];
#pragma unroll
            for (int i=0;i<TM;++i) a[i] = As[kk][ty*TM + i];
#pragma unroll
            for (int j=0;j<TN;++j) b[j] = Bs[kk][tx*TN + j];
#pragma unroll
            for (int i=0;i<TM;++i)
#pragma unroll
                for (int j=0;j<TN;++j)
                    acc[i][j] = fmaf(a[i], b[j], acc[i][j]);
        }
        __syncthreads();
    }

#pragma unroll
    for (int i=0;i<TM;++i) {
        int gm = row0 + ty*TM + i;
        if (gm >= M) continue;
#pragma unroll
        for (int j=0;j<TN;++j) {
            int gn = col0 + tx*TN + j;
            if (gn >= N) continue;
            long long off = (long long)gm*N + gn;
            float v = acc[i][j];
            if (MODE == 0)      C[off] = v;
            else if (MODE == 1) C[off] += v;
            else if (MODE == 2) C[off] = 2.f*v - D[off];
            else {              // MODE 3: adjacency
                C[off] = expf(2.f*v - D[gm] - D[gn]);
            }
        }
    }
}

// ---------------- elementwise / reduction kernels ----------------
__global__ void concat_input_k(const float* __restrict__ x, const int* __restrict__ cat,
                               float* __restrict__ X0)
{
    int idx = blockIdx.x*blockDim.x + threadIdx.x;   // over B*N rows
    if (idx >= BB*NN) return;
    int b = idx / NN;
    float* o = X0 + (long long)idx*22;
    const float* xi = x + (long long)idx*6;
#pragma unroll
    for (int i=0;i<6;i++) o[i] = xi[i];
    int c = cat[b];
#pragma unroll
    for (int i=0;i<16;i++) o[6+i] = (i==c) ? 1.f : 0.f;
}

__device__ __forceinline__ float block_reduce_sum(float v)
{
    __shared__ float s[32];
    int lane = threadIdx.x & 31, wid = threadIdx.x >> 5;
#pragma unroll
    for (int o=16;o>0;o>>=1) v += __shfl_down_sync(0xffffffffu, v, o);
    if (lane == 0) s[wid] = v;
    __syncthreads();
    int nw = blockDim.x >> 5;
    v = (threadIdx.x < nw) ? s[threadIdx.x] : 0.f;
    if (wid == 0) {
#pragma unroll
        for (int o=16;o>0;o>>=1) v += __shfl_down_sync(0xffffffffu, v, o);
    }
    return v;
}

__global__ void row_sq_k(const float* __restrict__ X, float* __restrict__ sq, int F)
{
    const float* r = X + (long long)blockIdx.x * F;
    float s = 0.f;
    for (int i = threadIdx.x; i < F; i += blockDim.x) { float v = r[i]; s += v*v; }
    s = block_reduce_sum(s);
    if (threadIdx.x == 0) sq[blockIdx.x] = s;
}

__global__ void rowsum_dinv_k(const float* __restrict__ adj, float* __restrict__ dinv, int n)
{
    const float* r = adj + (long long)blockIdx.x * n;
    float s = 0.f;
    for (int i = threadIdx.x; i < n; i += blockDim.x) s += r[i];
    s = block_reduce_sum(s);
    if (threadIdx.x == 0) dinv[blockIdx.x] = rsqrtf(s);
}

__global__ void normalize_lap_k(float* __restrict__ L, const float* __restrict__ dinv)
{
    long long idx = (long long)blockIdx.x*blockDim.x + threadIdx.x;
    long long total = (long long)BB*NN*NN;
    if (idx >= total) return;
    int c = (int)(idx % NN);
    long long row = idx / NN;                  // b*NN + r
    int r = (int)(row % NN);
    float v = L[idx] * dinv[row] * dinv[row - r + c];
    L[idx] = (r == c) ? (1.f - v) : (-v);
}

__global__ void add_bias_k(float* __restrict__ p, const float* __restrict__ b, int total, int F)
{
    int i = blockIdx.x*blockDim.x + threadIdx.x;
    if (i < total) p[i] += b[i % F];
}

__global__ void relu_br_k(const float* __restrict__ src, float* __restrict__ dst,
                          const float* __restrict__ br, int total, int F)
{
    int i = blockIdx.x*blockDim.x + threadIdx.x;
    if (i < total) dst[i] = fmaxf(src[i] + br[i % F], 0.f);
}

__global__ void relu_2b_k(float* __restrict__ p, const float* __restrict__ b1,
                          const float* __restrict__ b2, int total, int F)
{
    int i = blockIdx.x*blockDim.x + threadIdx.x;
    if (i < total) { int f = i % F; p[i] = fmaxf(p[i] + b1[f] + b2[f], 0.f); }
}

// ---------------- host-side launch helpers ----------------
static inline void gemm_big(int mode, const float* A, const float* B, float* C, const float* D,
                            int M, int N, int K, int batch,
                            long long sA, long long sB, long long sC, long long sD)
{
    dim3 g((N+63)/64, (M+127)/128, batch);
    switch (mode) {
      case 0: gemm_k<128,64,16,8,4,0,false><<<g,256>>>(A,B,C,D,M,N,K,sA,sB,sC,sD); break;
      case 1: gemm_k<128,64,16,8,4,1,false><<<g,256>>>(A,B,C,D,M,N,K,sA,sB,sC,sD); break;
      case 2: gemm_k<128,64,16,8,4,2,false><<<g,256>>>(A,B,C,D,M,N,K,sA,sB,sC,sD); break;
      case 3: gemm_k<128,64,16,8,4,3,true ><<<g,256>>>(A,B,C,D,M,N,K,sA,sB,sC,sD); break;
    }
}

static inline void gemm_narrow(int mode, const float* A, const float* B, float* C, const float* D,
                               int M, int N, int K, int batch,
                               long long sA, long long sB, long long sC, long long sD)
{
    dim3 g((N+31)/32, (M+63)/64, batch);
    switch (mode) {
      case 0: gemm_k<64,32,16,4,4,0,false><<<g,128>>>(A,B,C,D,M,N,K,sA,sB,sC,sD); break;
      case 2: gemm_k<64,32,16,4,4,2,false><<<g,128>>>(A,B,C,D,M,N,K,sA,sB,sC,sD); break;
    }
}

extern "C" void kernel_launch(void* const* d_in, const int* in_sizes, int n_in,
                              void* d_out, int out_size)
{
    (void)in_sizes; (void)n_in; (void)out_size;

    const float* x   = (const float*)d_in[0];
    const int*   cat = (const int*)  d_in[1];
    const float* Wc[3] = {(const float*)d_in[2], (const float*)d_in[4], (const float*)d_in[6]};
    const float* bc[3] = {(const float*)d_in[3], (const float*)d_in[5], (const float*)d_in[7]};
    const float* fw[3] = {(const float*)d_in[8], (const float*)d_in[10], (const float*)d_in[12]};
    const float* fb[3] = {(const float*)d_in[9], (const float*)d_in[11], (const float*)d_in[13]};
    const float* br[6];
    for (int i=0;i<6;i++) br[i] = (const float*)d_in[14+i];
    float* out = (float*)d_out;

    float *L,*sqv,*dv,*X0,*Ta,*Tb,*pre,*act0,*skip,*act2,*fc0,*fc1;
    cudaGetSymbolAddress((void**)&L,   g_L);
    cudaGetSymbolAddress((void**)&sqv, g_sq);
    cudaGetSymbolAddress((void**)&dv,  g_dinv);
    cudaGetSymbolAddress((void**)&X0,  g_X0);
    cudaGetSymbolAddress((void**)&Ta,  g_Ta);
    cudaGetSymbolAddress((void**)&Tb,  g_Tb);
    cudaGetSymbolAddress((void**)&pre, g_pre);
    cudaGetSymbolAddress((void**)&act0,g_act0);
    cudaGetSymbolAddress((void**)&skip,g_skip);
    cudaGetSymbolAddress((void**)&act2,g_act2);
    cudaGetSymbolAddress((void**)&fc0, g_fc0);
    cudaGetSymbolAddress((void**)&fc1, g_fc1);

    const long long sL = (long long)NN*NN;

    // Laplacian from feature matrix `feat` [B, NN, F] (batched, contiguous)
    auto laplacian = [&](const float* feat, int F) {
        row_sq_k<<<BB*NN,128>>>(feat, sqv, F);
        gemm_big(3, feat, feat, L, sqv, NN, NN, F, BB,
                 (long long)NN*F, (long long)NN*F, sL, NN);
        rowsum_dinv_k<<<BB*NN,256>>>(L, dv, NN);
        long long total = (long long)BB*NN*NN;
        normalize_lap_k<<<(unsigned)((total+255)/256),256>>>(L, dv);
    };

    // Chebyshev conv: preOut[B*NN,F] = sum_k T_k @ W[k], then += bias
    auto cheb = [&](const float* X, int cin, const float* W, const float* bias,
                    int F, int K, float* preOut) {
        long long sT = (long long)NN*cin;
        // T0 = X : pre = X @ W[0]
        gemm_big(0, X, W, preOut, nullptr, BB*NN, F, cin, 1, 0,0,0,0);
        // T1 = L @ X
        if (cin <= 32)
            gemm_narrow(0, L, X, Ta, nullptr, NN, cin, NN, BB, sL, sT, sT, 0);
        else
            gemm_big(0, L, X, Ta, nullptr, NN, cin, NN, BB, sL, sT, sT, 0);
        gemm_big(1, Ta, W + (long long)cin*F, preOut, nullptr, BB*NN, F, cin, 1, 0,0,0,0);

        const float* Tprev = X;
        float* Tcur = Ta;
        for (int k = 2; k < K; ++k) {
            float* Tnext = (Tprev == X) ? Tb : (float*)Tprev;  // never clobber X
            if (cin <= 32)
                gemm_narrow(2, L, Tcur, Tnext, Tprev, NN, cin, NN, BB, sL, sT, sT, sT);
            else
                gemm_big(2, L, Tcur, Tnext, Tprev, NN, cin, NN, BB, sL, sT, sT, sT);
            Tprev = Tcur; Tcur = Tnext;
            gemm_big(1, Tcur, W + (long long)k*cin*F, preOut, nullptr, BB*NN, F, cin, 1, 0,0,0,0);
        }
        int total = BB*NN*F;
        add_bias_k<<<(total+255)/256,256>>>(preOut, bias, total, F);
    };

    // ---- input assembly + Laplacian from raw x (dim 6) ----
    concat_input_k<<<(BB*NN+127)/128,128>>>(x, cat, X0);
    laplacian(x, 6);

    // ---- conv 0: cin=22 -> F=128, K=6 ----
    cheb(X0, 22, Wc[0], bc[0], 128, 6, pre);
    laplacian(pre, 128);                                   // from pre-ReLU features
    relu_br_k<<<(BB*NN*128+255)/256,256>>>(pre, act0, br[0], BB*NN*128, 128);

    // ---- conv 1: cin=128 -> F=512, K=5 ----
    cheb(act0, 128, Wc[1], bc[1], 512, 5, pre);
    laplacian(pre, 512);
    relu_br_k<<<(BB*NN*512+255)/256,256>>>(pre, skip, br[1], BB*NN*512, 512);  // skip = x1_skip

    // ---- conv 2: cin=512 -> F=1024, K=3 (final Laplacian recompute unused -> skipped) ----
    cheb(skip, 512, Wc[2], bc[2], 1024, 3, pre);
    relu_br_k<<<(BB*NN*1024+255)/256,256>>>(pre, act2, br[2], BB*NN*1024, 1024);

    // ---- FC0: 1024 -> 512 ----
    gemm_big(0, act2, fw[0], fc0, nullptr, BB*NN, 512, 1024, 1, 0,0,0,0);
    relu_2b_k<<<(BB*NN*512+255)/256,256>>>(fc0, fb[0], br[3], BB*NN*512, 512);

    // ---- FC1: concat(fc0, skip) [1024] -> 128, done as two accumulating GEMMs ----
    gemm_big(0, fc0,  fw[1],                     fc1, nullptr, BB*NN, 128, 512, 1, 0,0,0,0);
    gemm_big(1, skip, fw[1] + (long long)512*128, fc1, nullptr, BB*NN, 128, 512, 1, 0,0,0,0);
    relu_2b_k<<<(BB*NN*128+255)/256,256>>>(fc1, fb[1], br[4], BB*NN*128, 128);

    // ---- FC2: 128 -> 50, straight into d_out ----
    gemm_big(0, fc1, fw[2], out, nullptr, BB*NN, 50, 128, 1, 0,0,0,0);
    relu_2b_k<<<(BB*NN*50+255)/256,256>>>(out, fb[2], br[5], BB*NN*50, 50);
}

// round 4
// speedup vs baseline: 1.5296x; 1.5296x over previous
#include <cuda_runtime.h>
#include <math.h>

#define BB 8
#define NN 2048
#define NSPLIT 8

// ---------------- scratch (device globals; allocation-free) ----------------
__device__ float g_L   [BB*(size_t)NN*NN];
__device__ float g_sq  [BB*NN];
__device__ float g_dinv[BB*NN];
__device__ float g_X0  [BB*NN*22];
__device__ float g_Ta  [BB*NN*512];
__device__ float g_Tb  [BB*NN*512];
__device__ float g_pre [BB*NN*1024];
__device__ float g_act0[BB*NN*128];
__device__ float g_skip[BB*NN*512];
__device__ float g_act2[BB*NN*1024];
__device__ float g_fc0 [BB*NN*512];
__device__ float g_fc1 [BB*NN*128];
__device__ float g_part[(size_t)NSPLIT*BB*NN*24];

// ---------------- f32x2 helpers (Blackwell packed fp32) ----------------
__device__ __forceinline__ unsigned long long pk2(float x) {
    unsigned long long r;
    unsigned xi = __float_as_uint(x);
    asm("mov.b64 %0, {%1, %1};" : "=l"(r) : "r"(xi));
    return r;
}
__device__ __forceinline__ void fma2(unsigned long long& d, unsigned long long a, unsigned long long b) {
    asm("fma.rn.f32x2 %0, %1, %2, %0;" : "+l"(d) : "l"(a), "l"(b));
}
__device__ __forceinline__ float lo32(unsigned long long v){ return __uint_as_float((unsigned)v); }
__device__ __forceinline__ float hi32(unsigned long long v){ return __uint_as_float((unsigned)(v>>32)); }

// ---------------- main f32x2 SGEMM ----------------
// Requires M%BM==0, N%BN==0, K%16==0.
// EPI: 0 C=v | 1 C+=v | 2 C=2v-D | 3 C=exp(2v-D[m]-D[n]) (TB) | 4 C=v+b1[n]
//      5 C=relu(v+b1[n]+b2[n]) | 6 C=relu(C+v+b1[n]+b2[n])
template<int BM,int BN,int TM,int TN,int EPI,bool TB>
__global__ void __launch_bounds__(256)
gemm2_k(const float* __restrict__ A, const float* __restrict__ Bm,
        float* __restrict__ C, const float* __restrict__ D,
        const float* __restrict__ b1, const float* __restrict__ b2,
        int M, int N, int K,
        long long sA, long long sB, long long sC, long long sD)
{
    constexpr int BK = 16;
    constexpr int TX = BN/TN;       // threads along n
    const int bz = blockIdx.z;
    A  += (long long)bz * sA;
    Bm += (long long)bz * sB;
    C  += (long long)bz * sC;
    const float* Dp = D ? D + (long long)bz * sD : (const float*)0;

    const int row0 = blockIdx.y * BM;
    const int col0 = blockIdx.x * BN;

    __shared__ float As[BK][BM+4];
    __shared__ float Bs[BK][BN+4];

    const int tid = threadIdx.x;
    const int tx  = tid % TX;
    const int ty  = tid / TX;

    unsigned long long acc[TM][TN/2];
#pragma unroll
    for (int i=0;i<TM;i++)
#pragma unroll
        for (int j=0;j<TN/2;j++) acc[i][j] = 0ull;

    for (int k0 = 0; k0 < K; k0 += BK) {
        // ---- A tile: BM x 16, float4 along k, store transposed ----
#pragma unroll
        for (int p = 0; p < (BM*4)/256; ++p) {
            int q  = tid + p*256;
            int m  = q >> 2;
            int kq = (q & 3) * 4;
            float4 v = *(const float4*)(A + (long long)(row0+m)*K + (k0+kq));
            As[kq+0][m]=v.x; As[kq+1][m]=v.y; As[kq+2][m]=v.z; As[kq+3][m]=v.w;
        }
        // ---- B tile ----
        if (TB) {
            // B [N,K] row-major: float4 along k, store transposed
#pragma unroll
            for (int p = 0; p < (BN*4)/256; ++p) {
                int q  = tid + p*256;
                int n  = q >> 2;
                int kq = (q & 3) * 4;
                float4 v = *(const float4*)(Bm + (long long)(col0+n)*K + (k0+kq));
                Bs[kq+0][n]=v.x; Bs[kq+1][n]=v.y; Bs[kq+2][n]=v.z; Bs[kq+3][n]=v.w;
            }
        } else {
            // B [K,N] row-major: float4 along n
            constexpr int QPR = BN/4;
#pragma unroll
            for (int p = 0; p < (16*QPR)/256; ++p) {
                int q  = tid + p*256;
                int kk = q / QPR;
                int n4 = (q % QPR) * 4;
                *(float4*)&Bs[kk][n4] = *(const float4*)(Bm + (long long)(k0+kk)*N + (col0+n4));
            }
        }
        __syncthreads();

#pragma unroll
        for (int kk = 0; kk < BK; ++kk) {
            float4 a0 = *(const float4*)&As[kk][ty*TM];
            float4 a1;
            if (TM == 8) a1 = *(const float4*)&As[kk][ty*TM+4];
            unsigned long long ad[TM];
            ad[0]=pk2(a0.x); ad[1]=pk2(a0.y); ad[2]=pk2(a0.z); ad[3]=pk2(a0.w);
            if (TM == 8) { ad[4]=pk2(a1.x); ad[5]=pk2(a1.y); ad[6]=pk2(a1.z); ad[7]=pk2(a1.w); }

            unsigned long long bp[TN/2];
            {
                ulonglong2 v = *(const ulonglong2*)&Bs[kk][tx*TN];
                bp[0]=v.x; bp[1]=v.y;
                if (TN == 8) {
                    ulonglong2 w = *(const ulonglong2*)&Bs[kk][tx*TN+4];
                    bp[2]=w.x; bp[3]=w.y;
                }
            }
#pragma unroll
            for (int i=0;i<TM;++i)
#pragma unroll
                for (int j=0;j<TN/2;++j)
                    fma2(acc[i][j], ad[i], bp[j]);
        }
        __syncthreads();
    }

    // ---- epilogue ----
#pragma unroll
    for (int i=0;i<TM;++i) {
        int gm = row0 + ty*TM + i;
        long long rb = (long long)gm * N;
#pragma unroll
        for (int j=0;j<TN/2;++j) {
            int gn = col0 + tx*TN + 2*j;
            float v0 = lo32(acc[i][j]);
            float v1 = hi32(acc[i][j]);
            long long o0 = rb + gn;
            if (EPI == 0)      { C[o0] = v0; C[o0+1] = v1; }
            else if (EPI == 1) { C[o0] += v0; C[o0+1] += v1; }
            else if (EPI == 2) { C[o0] = 2.f*v0 - Dp[o0]; C[o0+1] = 2.f*v1 - Dp[o0+1]; }
            else if (EPI == 3) {
                float dm = Dp[gm];
                C[o0]   = expf(2.f*v0 - dm - Dp[gn]);
                C[o0+1] = expf(2.f*v1 - dm - Dp[gn+1]);
            }
            else if (EPI == 4) { C[o0] = v0 + b1[gn]; C[o0+1] = v1 + b1[gn+1]; }
            else if (EPI == 5) {
                C[o0]   = fmaxf(v0 + b1[gn]   + b2[gn],   0.f);
                C[o0+1] = fmaxf(v1 + b1[gn+1] + b2[gn+1], 0.f);
            }
            else { // 6
                C[o0]   = fmaxf(C[o0]   + v0 + b1[gn]   + b2[gn],   0.f);
                C[o0+1] = fmaxf(C[o0+1] + v1 + b1[gn+1] + b2[gn+1], 0.f);
            }
        }
    }
}

// ---------------- legacy tiled SGEMM (small/odd shapes) ----------------
// MODE 0: C=A@B | 1: C+=A@B | 2: C=2A@B-D | 3: C=exp(2A@B^T - sq_i - sq_j)
template<int BM,int BN,int BK,int TM,int TN,int MODE,bool TB>
__global__ void __launch_bounds__((BM/TM)*(BN/TN))
gemm_k(const float* __restrict__ A, const float* __restrict__ Bm,
       float* C, const float* D,
       int M, int N, int K,
       long long sA, long long sB, long long sC, long long sD)
{
    constexpr int NT = (BM/TM)*(BN/TN);
    const int bz = blockIdx.z;
    A  += (long long)bz * sA;
    Bm += (long long)bz * sB;
    C  += (long long)bz * sC;
    if (D) D += (long long)bz * sD;

    const int row0 = blockIdx.y * BM;
    const int col0 = blockIdx.x * BN;

    __shared__ float As[BK][BM+4];
    __shared__ float Bs[BK][BN+4];

    const int tid = threadIdx.x;
    const int tx  = tid % (BN/TN);
    const int ty  = tid / (BN/TN);

    float acc[TM][TN];
#pragma unroll
    for (int i=0;i<TM;i++)
#pragma unroll
        for (int j=0;j<TN;j++) acc[i][j] = 0.f;

    for (int k0 = 0; k0 < K; k0 += BK) {
#pragma unroll
        for (int idx = tid; idx < BM*BK; idx += NT) {
            int m  = idx / BK, kk = idx % BK;
            int gm = row0 + m, gk = k0 + kk;
            As[kk][m] = (gm < M && gk < K) ? A[(long long)gm*K + gk] : 0.f;
        }
        if (TB) {
#pragma unroll
            for (int idx = tid; idx < BK*BN; idx += NT) {
                int n  = idx / BK, kk = idx % BK;
                int gn = col0 + n, gk = k0 + kk;
                Bs[kk][n] = (gn < N && gk < K) ? Bm[(long long)gn*K + gk] : 0.f;
            }
        } else {
#pragma unroll
            for (int idx = tid; idx < BK*BN; idx += NT) {
                int kk = idx / BN, n = idx % BN;
                int gk = k0 + kk, gn = col0 + n;
                Bs[kk][n] = (gk < K && gn < N) ? Bm[(long long)gk*N + gn] : 0.f;
            }
        }
        __syncthreads();
#pragma unroll
        for (int kk = 0; kk < BK; ++kk) {
            float a[TM], b[TN];
#pragma unroll
            for (int i=0;i<TM;++i) a[i] = As[kk][ty*TM + i];
#pragma unroll
            for (int j=0;j<TN;++j) b[j] = Bs[kk][tx*TN + j];
#pragma unroll
            for (int i=0;i<TM;++i)
#pragma unroll
                for (int j=0;j<TN;++j)
                    acc[i][j] = fmaf(a[i], b[j], acc[i][j]);
        }
        __syncthreads();
    }
#pragma unroll
    for (int i=0;i<TM;++i) {
        int gm = row0 + ty*TM + i;
        if (gm >= M) continue;
#pragma unroll
        for (int j=0;j<TN;++j) {
            int gn = col0 + tx*TN + j;
            if (gn >= N) continue;
            long long off = (long long)gm*N + gn;
            float v = acc[i][j];
            if (MODE == 0)      C[off] = v;
            else if (MODE == 1) C[off] += v;
            else if (MODE == 2) C[off] = 2.f*v - D[off];
            else                C[off] = expf(2.f*v - D[gm] - D[gn]);
        }
    }
}

// ---------------- narrow L@T (cin=22) via symmetry of L, split-K ----------------
// partial[s][b][row][c] = sum_{k in chunk s} L[b][k][row] * T[b][k][c]   (L symmetric)
__global__ void __launch_bounds__(256)
lx_part_k(const float* __restrict__ L, const float* __restrict__ T, float* __restrict__ part)
{
    const int b = blockIdx.z;
    const int s = blockIdx.y;
    const int r0 = blockIdx.x * 512 + threadIdx.x * 2;   // two rows per thread
    const float* Lb = L + (long long)b*NN*NN;
    const float* Tp = T + (long long)b*NN*22;

    __shared__ float Tsh[32][24];
    unsigned long long accA[11], accB[11];
#pragma unroll
    for (int j=0;j<11;j++){ accA[j]=0ull; accB[j]=0ull; }

    const int kbeg = s * (NN/NSPLIT);
    const int kend = kbeg + (NN/NSPLIT);
    for (int k0 = kbeg; k0 < kend; k0 += 32) {
        for (int idx = threadIdx.x; idx < 32*22; idx += 256) {
            int kk = idx / 22, c = idx % 22;
            Tsh[kk][c] = Tp[(long long)(k0+kk)*22 + c];
        }
        __syncthreads();
#pragma unroll
        for (int kk = 0; kk < 32; ++kk) {
            float2 l2 = *(const float2*)(Lb + (long long)(k0+kk)*NN + r0);
            unsigned long long lx = pk2(l2.x), ly = pk2(l2.y);
#pragma unroll
            for (int j=0;j<11;j++) {
                unsigned long long tp = *(const unsigned long long*)&Tsh[kk][2*j];
                fma2(accA[j], lx, tp);
                fma2(accB[j], ly, tp);
            }
        }
        __syncthreads();
    }
    float* p = part + ((long long)(s*BB + b)*NN)*24;
#pragma unroll
    for (int j=0;j<11;j++) {
        p[(long long)r0*24     + 2*j]   = lo32(accA[j]);
        p[(long long)r0*24     + 2*j+1] = hi32(accA[j]);
        p[(long long)(r0+1)*24 + 2*j]   = lo32(accB[j]);
        p[(long long)(r0+1)*24 + 2*j+1] = hi32(accB[j]);
    }
}

// mode 0: T = sum_s partial ; mode 2: T = 2*sum - Tprev  (Tout may alias Tprev)
__global__ void lx_reduce_k(const float* __restrict__ part, float* __restrict__ Tout,
                            const float* __restrict__ Tprev, int mode)
{
    int idx = blockIdx.x*blockDim.x + threadIdx.x;
    if (idx >= BB*NN*22) return;
    int c   = idx % 22;
    int row = idx / 22;                  // b*NN + i
    float s = 0.f;
#pragma unroll
    for (int k=0;k<NSPLIT;k++)
        s += part[((long long)k*BB*NN + row)*24 + c];
    float v = (mode == 2) ? (2.f*s - Tprev[(long long)row*22 + c]) : s;
    Tout[(long long)row*22 + c] = v;
}

// ---------------- elementwise / reductions ----------------
__global__ void concat_input_k(const float* __restrict__ x, const int* __restrict__ cat,
                               float* __restrict__ X0)
{
    int idx = blockIdx.x*blockDim.x + threadIdx.x;
    if (idx >= BB*NN) return;
    int b = idx / NN;
    float* o = X0 + (long long)idx*22;
    const float* xi = x + (long long)idx*6;
#pragma unroll
    for (int i=0;i<6;i++) o[i] = xi[i];
    int c = cat[b];
#pragma unroll
    for (int i=0;i<16;i++) o[6+i] = (i==c) ? 1.f : 0.f;
}

__device__ __forceinline__ float block_reduce_sum(float v)
{
    __shared__ float s[32];
    int lane = threadIdx.x & 31, wid = threadIdx.x >> 5;
#pragma unroll
    for (int o=16;o>0;o>>=1) v += __shfl_down_sync(0xffffffffu, v, o);
    if (lane == 0) s[wid] = v;
    __syncthreads();
    int nw = blockDim.x >> 5;
    v = (threadIdx.x < nw) ? s[threadIdx.x] : 0.f;
    if (wid == 0) {
#pragma unroll
        for (int o=16;o>0;o>>=1) v += __shfl_down_sync(0xffffffffu, v, o);
    }
    return v;
}

__global__ void row_sq_k(const float* __restrict__ X, float* __restrict__ sq, int F)
{
    const float* r = X + (long long)blockIdx.x * F;
    float s = 0.f;
    for (int i = threadIdx.x; i < F; i += blockDim.x) { float v = r[i]; s += v*v; }
    s = block_reduce_sum(s);
    if (threadIdx.x == 0) sq[blockIdx.x] = s;
}

__global__ void row_sq_v4_k(const float* __restrict__ X, float* __restrict__ sq, int F4)
{
    const float4* r = (const float4*)X + (long long)blockIdx.x * F4;
    float s = 0.f;
    for (int i = threadIdx.x; i < F4; i += blockDim.x) {
        float4 v = r[i];
        s += v.x*v.x + v.y*v.y + v.z*v.z + v.w*v.w;
    }
    s = block_reduce_sum(s);
    if (threadIdx.x == 0) sq[blockIdx.x] = s;
}

__global__ void rowsum_dinv_v4_k(const float* __restrict__ adj, float* __restrict__ dinv)
{
    const float4* r = (const float4*)(adj + (long long)blockIdx.x * NN);
    float s = 0.f;
    for (int i = threadIdx.x; i < NN/4; i += blockDim.x) {
        float4 v = r[i]; s += v.x + v.y + v.z + v.w;
    }
    s = block_reduce_sum(s);
    if (threadIdx.x == 0) dinv[blockIdx.x] = rsqrtf(s);
}

__global__ void normalize_v4_k(float* __restrict__ L, const float* __restrict__ dinv)
{
    long long i4 = (long long)blockIdx.x*blockDim.x + threadIdx.x;
    long long tot4 = (long long)BB*NN*NN/4;
    if (i4 >= tot4) return;
    long long base = i4*4;
    int c = (int)(base % NN);
    long long row = base / NN;
    int r = (int)(row % NN);
    float dr = dinv[row];
    const float* dc = dinv + (row - r);
    float4 v = ((const float4*)L)[i4];
    v.x *= dr*dc[c];   v.y *= dr*dc[c+1];
    v.z *= dr*dc[c+2]; v.w *= dr*dc[c+3];
    float4 o;
    o.x = (r==c  ) ? 1.f-v.x : -v.x;
    o.y = (r==c+1) ? 1.f-v.y : -v.y;
    o.z = (r==c+2) ? 1.f-v.z : -v.z;
    o.w = (r==c+3) ? 1.f-v.w : -v.w;
    ((float4*)L)[i4] = o;
}

__global__ void add_bias_v4_k(float* __restrict__ p, const float* __restrict__ b, int total4, int F)
{
    int i = blockIdx.x*blockDim.x + threadIdx.x;
    if (i >= total4) return;
    int f = (i*4) % F;
    float4 v = ((float4*)p)[i];
    v.x += b[f]; v.y += b[f+1]; v.z += b[f+2]; v.w += b[f+3];
    ((float4*)p)[i] = v;
}

__global__ void relu_br_v4_k(const float* __restrict__ src, float* __restrict__ dst,
                             const float* __restrict__ br, int total4, int F)
{
    int i = blockIdx.x*blockDim.x + threadIdx.x;
    if (i >= total4) return;
    int f = (i*4) % F;
    float4 v = ((const float4*)src)[i];
    v.x = fmaxf(v.x + br[f],   0.f);
    v.y = fmaxf(v.y + br[f+1], 0.f);
    v.z = fmaxf(v.z + br[f+2], 0.f);
    v.w = fmaxf(v.w + br[f+3], 0.f);
    ((float4*)dst)[i] = v;
}

__global__ void relu_2b_k(float* __restrict__ p, const float* __restrict__ b1,
                          const float* __restrict__ b2, int total, int F)
{
    int i = blockIdx.x*blockDim.x + threadIdx.x;
    if (i < total) { int f = i % F; p[i] = fmaxf(p[i] + b1[f] + b2[f], 0.f); }
}

// ---------------- host helpers ----------------
static inline void gemm_big(int mode, const float* A, const float* B, float* C, const float* D,
                            int M, int N, int K, int batch,
                            long long sA, long long sB, long long sC, long long sD)
{
    dim3 g((N+63)/64, (M+127)/128, batch);
    switch (mode) {
      case 0: gemm_k<128,64,16,8,4,0,false><<<g,256>>>(A,B,C,D,M,N,K,sA,sB,sC,sD); break;
      case 1: gemm_k<128,64,16,8,4,1,false><<<g,256>>>(A,B,C,D,M,N,K,sA,sB,sC,sD); break;
      case 3: gemm_k<128,64,16,8,4,3,true ><<<g,256>>>(A,B,C,D,M,N,K,sA,sB,sC,sD); break;
    }
}

static inline void gemm2_w(int epi, const float* A, const float* B, float* C, const float* D,
                           const float* b1, const float* b2,
                           int M, int N, int K, int batch,
                           long long sA, long long sB, long long sC, long long sD)
{
    dim3 g(N/128, M/128, batch);
    switch (epi) {
      case 0: gemm2_k<128,128,8,8,0,false><<<g,256>>>(A,B,C,D,b1,b2,M,N,K,sA,sB,sC,sD); break;
      case 1: gemm2_k<128,128,8,8,1,false><<<g,256>>>(A,B,C,D,b1,b2,M,N,K,sA,sB,sC,sD); break;
      case 2: gemm2_k<128,128,8,8,2,false><<<g,256>>>(A,B,C,D,b1,b2,M,N,K,sA,sB,sC,sD); break;
      case 3: gemm2_k<128,128,8,8,3,true ><<<g,256>>>(A,B,C,D,b1,b2,M,N,K,sA,sB,sC,sD); break;
      case 4: gemm2_k<128,128,8,8,4,false><<<g,256>>>(A,B,C,D,b1,b2,M,N,K,sA,sB,sC,sD); break;
      case 5: gemm2_k<128,128,8,8,5,false><<<g,256>>>(A,B,C,D,b1,b2,M,N,K,sA,sB,sC,sD); break;
    }
}

static inline void gemm2_n64(int epi, const float* A, const float* B, float* C, const float* D,
                             const float* b1, const float* b2,
                             int M, int N, int K, int batch,
                             long long sA, long long sB, long long sC, long long sD)
{
    dim3 g(N/64, M/128, batch);
    switch (epi) {
      case 0: gemm2_k<128,64,8,4,0,false><<<g,256>>>(A,B,C,D,b1,b2,M,N,K,sA,sB,sC,sD); break;
      case 2: gemm2_k<128,64,8,4,2,false><<<g,256>>>(A,B,C,D,b1,b2,M,N,K,sA,sB,sC,sD); break;
      case 6: gemm2_k<128,64,8,4,6,false><<<g,256>>>(A,B,C,D,b1,b2,M,N,K,sA,sB,sC,sD); break;
    }
}

extern "C" void kernel_launch(void* const* d_in, const int* in_sizes, int n_in,
                              void* d_out, int out_size)
{
    (void)in_sizes; (void)n_in; (void)out_size;

    const float* x   = (const float*)d_in[0];
    const int*   cat = (const int*)  d_in[1];
    const float* Wc[3] = {(const float*)d_in[2], (const float*)d_in[4], (const float*)d_in[6]};
    const float* bc[3] = {(const float*)d_in[3], (const float*)d_in[5], (const float*)d_in[7]};
    const float* fw[3] = {(const float*)d_in[8], (const float*)d_in[10], (const float*)d_in[12]};
    const float* fb[3] = {(const float*)d_in[9], (const float*)d_in[11], (const float*)d_in[13]};
    const float* br[6];
    for (int i=0;i<6;i++) br[i] = (const float*)d_in[14+i];
    float* out = (float*)d_out;

    float *L,*sqv,*dv,*X0,*Ta,*Tb,*pre,*act0,*skip,*act2,*fc0,*fc1,*part;
    cudaGetSymbolAddress((void**)&L,   g_L);
    cudaGetSymbolAddress((void**)&sqv, g_sq);
    cudaGetSymbolAddress((void**)&dv,  g_dinv);
    cudaGetSymbolAddress((void**)&X0,  g_X0);
    cudaGetSymbolAddress((void**)&Ta,  g_Ta);
    cudaGetSymbolAddress((void**)&Tb,  g_Tb);
    cudaGetSymbolAddress((void**)&pre, g_pre);
    cudaGetSymbolAddress((void**)&act0,g_act0);
    cudaGetSymbolAddress((void**)&skip,g_skip);
    cudaGetSymbolAddress((void**)&act2,g_act2);
    cudaGetSymbolAddress((void**)&fc0, g_fc0);
    cudaGetSymbolAddress((void**)&fc1, g_fc1);
    cudaGetSymbolAddress((void**)&part,g_part);

    const long long sL = (long long)NN*NN;
    const long long tot4 = (long long)BB*NN*NN/4;

    // Laplacian from features [B,NN,F]
    auto laplacian = [&](const float* feat, int F) {
        if (F % 4 == 0) {
            row_sq_v4_k<<<BB*NN,128>>>(feat, sqv, F/4);
            gemm2_w(3, feat, feat, L, sqv, 0, 0, NN, NN, F, BB,
                    (long long)NN*F, (long long)NN*F, sL, NN);
        } else {
            row_sq_k<<<BB*NN,64>>>(feat, sqv, F);
            gemm_big(3, feat, feat, L, sqv, NN, NN, F, BB,
                     (long long)NN*F, (long long)NN*F, sL, NN);
        }
        rowsum_dinv_v4_k<<<BB*NN,256>>>(L, dv);
        normalize_v4_k<<<(unsigned)((tot4+255)/256),256>>>(L, dv);
    };

    // narrow cin=22 L@T via symmetric split-K
    auto lx22 = [&](int mode, const float* Tin, float* Tout, const float* Tprev) {
        dim3 g(NN/512, NSPLIT, BB);
        lx_part_k<<<g,256>>>(L, Tin, part);
        lx_reduce_k<<<(BB*NN*22+255)/256,256>>>(part, Tout, Tprev, mode);
    };

    // ---- input assembly + Laplacian from raw x (F=6) ----
    concat_input_k<<<(BB*NN+127)/128,128>>>(x, cat, X0);
    laplacian(x, 6);

    // ---- conv 0: cin=22 -> F=128, K=6 ----
    {
        gemm_big(0, X0, Wc[0], pre, nullptr, BB*NN, 128, 22, 1, 0,0,0,0);
        lx22(0, X0, Ta, nullptr);
        gemm_big(1, Ta, Wc[0] + 1*22*128, pre, nullptr, BB*NN, 128, 22, 1, 0,0,0,0);
        const float* Tprev = X0; float* Tcur = Ta;
        for (int k = 2; k < 6; ++k) {
            float* Tnext = (Tprev == X0) ? Tb : (float*)Tprev;
            lx22(2, Tcur, Tnext, Tprev);
            Tprev = Tcur; Tcur = Tnext;
            gemm_big(1, Tcur, Wc[0] + (long long)k*22*128, pre, nullptr, BB*NN, 128, 22, 1, 0,0,0,0);
        }
        add_bias_v4_k<<<(BB*NN*128/4+255)/256,256>>>(pre, bc[0], BB*NN*128/4, 128);
    }
    laplacian(pre, 128);
    relu_br_v4_k<<<(BB*NN*128/4+255)/256,256>>>(pre, act0, br[0], BB*NN*128/4, 128);

    // ---- conv 1: cin=128 -> F=512, K=5 ----
    {
        const int cin = 128, F = 512;
        long long sT = (long long)NN*cin;
        gemm2_w(4, act0, Wc[1], pre, 0, bc[1], 0, BB*NN, F, cin, 1, 0,0,0,0);
        gemm2_n64(0, L, act0, Ta, 0, 0, 0, NN, cin, NN, BB, sL, sT, sT, 0);
        gemm2_w(1, Ta, Wc[1] + (long long)cin*F, pre, 0, 0, 0, BB*NN, F, cin, 1, 0,0,0,0);
        const float* Tprev = act0; float* Tcur = Ta;
        for (int k = 2; k < 5; ++k) {
            float* Tnext = (Tprev == act0) ? Tb : (float*)Tprev;
            gemm2_n64(2, L, Tcur, Tnext, Tprev, 0, 0, NN, cin, NN, BB, sL, sT, sT, sT);
            Tprev = Tcur; Tcur = Tnext;
            gemm2_w(1, Tcur, Wc[1] + (long long)k*cin*F, pre, 0, 0, 0, BB*NN, F, cin, 1, 0,0,0,0);
        }
    }
    laplacian(pre, 512);
    relu_br_v4_k<<<(BB*NN*512/4+255)/256,256>>>(pre, skip, br[1], BB*NN*512/4, 512);

    // ---- conv 2: cin=512 -> F=1024, K=3 (trailing Laplacian unused -> skipped) ----
    {
        const int cin = 512, F = 1024;
        long long sT = (long long)NN*cin;
        gemm2_w(4, skip, Wc[2], pre, 0, bc[2], 0, BB*NN, F, cin, 1, 0,0,0,0);
        gemm2_w(0, L, skip, Ta, 0, 0, 0, NN, cin, NN, BB, sL, sT, sT, 0);
        gemm2_w(1, Ta, Wc[2] + (long long)cin*F, pre, 0, 0, 0, BB*NN, F, cin, 1, 0,0,0,0);
        gemm2_w(2, L, Ta, Tb, skip, 0, 0, NN, cin, NN, BB, sL, sT, sT, sT);
        gemm2_w(1, Tb, Wc[2] + (long long)2*cin*F, pre, 0, 0, 0, BB*NN, F, cin, 1, 0,0,0,0);
    }
    relu_br_v4_k<<<(BB*NN*1024/4+255)/256,256>>>(pre, act2, br[2], BB*NN*1024/4, 1024);

    // ---- FC0: 1024 -> 512 (bias+br+relu fused) ----
    gemm2_w(5, act2, fw[0], fc0, 0, fb[0], br[3], BB*NN, 512, 1024, 1, 0,0,0,0);

    // ---- FC1: concat(fc0, skip) -> 128 as two GEMMs; second fuses bias+br+relu ----
    gemm2_n64(0, fc0,  fw[1],                      fc1, 0, 0, 0,          BB*NN, 128, 512, 1, 0,0,0,0);
    gemm2_n64(6, skip, fw[1] + (long long)512*128, fc1, 0, fb[1], br[4],  BB*NN, 128, 512, 1, 0,0,0,0);

    // ---- FC2: 128 -> 50 ----
    gemm_big(0, fc1, fw[2], out, nullptr, BB*NN, 50, 128, 1, 0,0,0,0);
    relu_2b_k<<<(BB*NN*50+255)/256,256>>>(out, fb[2], br[5], BB*NN*50, 50);
}